// round 3
// baseline (speedup 1.0000x reference)
#include <cuda_runtime.h>
#include <cuda_bf16.h>
#include <math.h>

// ---------------------------------------------------------------------------
// SelfAttention_39676907883685  (B=4, T=2048, D=2048, HEADS=16)
//
// Pipeline:
//   kv  = x @ w_qk^T                      (8192 x 4096)
//   s[b]= k0[b]^T @ v[b]^T * scale        (4 x 2048 x 2048)
//   a   = softmax(s, axis=-1)
//   q[b]= a[b] @ v[b]                     (4 x 2048 x 2048)
//   out = gather_perm(q) @ w_dense^T + b  (8192 x 2048)
//
// Scratch lives in ONE __device__ global; kernels index it directly via
// offsets passed as arguments, so kernel_launch performs ONLY kernel
// launches (maximally graph-capture-safe).
// ---------------------------------------------------------------------------

#define BM 128
#define BN 128
#define BK 16
#define TM 8
#define TN 8
#define NTHREADS 256

// Layout inside g_scratch (floats):
//   kv : [0,               33554432)   8192 x 4096
//   s  : [33554432,        50331648)   4 x 2048 x 2048  (softmax in place)
//   q  : [50331648,        67108864)   4 x 2048 x 2048
#define OFF_KV 0L
#define OFF_S  33554432L
#define OFF_Q  50331648L
__device__ float g_scratch[67108864];   // 268 MB

// ---------------------------------------------------------------------------
// Generic tiled SGEMM:
//   C[m,n] = alpha * sum_k opA(m,k) * opB(k,n)
//   !TA: opA(m,k)=A[m*lda+k]      TA: opA(m,k)=A[k*lda+m]
//   !TB: opB(k,n)=B[k*ldb+n]      TB: opB(k,n)=B[n*ldb+k]
// A/B may be external (Aext != nullptr) or scratch at aOff.
// C is always scratch at cOff. All dims multiples of 128/BK.
// ---------------------------------------------------------------------------
template<bool TA, bool TB>
__global__ __launch_bounds__(NTHREADS)
void sgemm_kernel(const float* __restrict__ Aext, long aOff,
                  const float* __restrict__ Bext, long bOff,
                  long cOff,
                  int M, int N, int K, int lda, int ldb, int ldc,
                  long sA, long sB, long sC, float alpha)
{
    __shared__ float As[BK][BM];
    __shared__ float Bs[BK][BN];

    const float* A = (Aext ? Aext : g_scratch + aOff) + (long)blockIdx.z * sA;
    const float* B = (Bext ? Bext : g_scratch + bOff) + (long)blockIdx.z * sB;
    float*       C = g_scratch + cOff + (long)blockIdx.z * sC;

    const int bm = blockIdx.y * BM;
    const int bn = blockIdx.x * BN;
    const int tid = threadIdx.x;
    const int tx = tid & 15;   // n-dim
    const int ty = tid >> 4;   // m-dim

    float acc[TM][TN] = {};

    for (int k0 = 0; k0 < K; k0 += BK) {
        // ---- load A tile (128 x 16) into As[k][m] ----
        if (TA) {
            // A[k*lda+m]: contiguous in m. 16 k-rows, 2 per thread-group.
            const int k  = tid >> 5;           // 0..7
            const int m4 = (tid & 31) * 4;     // 0..124
            float4 v0 = *reinterpret_cast<const float4*>(
                &A[(long)(k0 + k) * lda + bm + m4]);
            float4 v1 = *reinterpret_cast<const float4*>(
                &A[(long)(k0 + k + 8) * lda + bm + m4]);
            *reinterpret_cast<float4*>(&As[k][m4])     = v0;
            *reinterpret_cast<float4*>(&As[k + 8][m4]) = v1;
        } else {
            // A[m*lda+k]: contiguous in k -> transpose on store.
            const int m  = tid >> 1;           // 0..127
            const int k8 = (tid & 1) * 8;      // 0 or 8
            float4 v0 = *reinterpret_cast<const float4*>(
                &A[(long)(bm + m) * lda + k0 + k8]);
            float4 v1 = *reinterpret_cast<const float4*>(
                &A[(long)(bm + m) * lda + k0 + k8 + 4]);
            As[k8 + 0][m] = v0.x; As[k8 + 1][m] = v0.y;
            As[k8 + 2][m] = v0.z; As[k8 + 3][m] = v0.w;
            As[k8 + 4][m] = v1.x; As[k8 + 5][m] = v1.y;
            As[k8 + 6][m] = v1.z; As[k8 + 7][m] = v1.w;
        }
        // ---- load B tile (16 x 128) into Bs[k][n] ----
        if (TB) {
            const int n  = tid >> 1;
            const int k8 = (tid & 1) * 8;
            float4 v0 = *reinterpret_cast<const float4*>(
                &B[(long)(bn + n) * ldb + k0 + k8]);
            float4 v1 = *reinterpret_cast<const float4*>(
                &B[(long)(bn + n) * ldb + k0 + k8 + 4]);
            Bs[k8 + 0][n] = v0.x; Bs[k8 + 1][n] = v0.y;
            Bs[k8 + 2][n] = v0.z; Bs[k8 + 3][n] = v0.w;
            Bs[k8 + 4][n] = v1.x; Bs[k8 + 5][n] = v1.y;
            Bs[k8 + 6][n] = v1.z; Bs[k8 + 7][n] = v1.w;
        } else {
            const int k  = tid >> 5;
            const int n4 = (tid & 31) * 4;
            float4 v0 = *reinterpret_cast<const float4*>(
                &B[(long)(k0 + k) * ldb + bn + n4]);
            float4 v1 = *reinterpret_cast<const float4*>(
                &B[(long)(k0 + k + 8) * ldb + bn + n4]);
            *reinterpret_cast<float4*>(&Bs[k][n4])     = v0;
            *reinterpret_cast<float4*>(&Bs[k + 8][n4]) = v1;
        }
        __syncthreads();

        #pragma unroll
        for (int k = 0; k < BK; k++) {
            float af[TM], bf[TN];
            #pragma unroll
            for (int i = 0; i < TM; i++) af[i] = As[k][ty * TM + i];
            #pragma unroll
            for (int j = 0; j < TN; j++) bf[j] = Bs[k][tx * TN + j];
            #pragma unroll
            for (int i = 0; i < TM; i++)
                #pragma unroll
                for (int j = 0; j < TN; j++)
                    acc[i][j] = fmaf(af[i], bf[j], acc[i][j]);
        }
        __syncthreads();
    }

    #pragma unroll
    for (int i = 0; i < TM; i++) {
        const long m = bm + ty * TM + i;
        #pragma unroll
        for (int j = 0; j < TN; j += 4) {
            float4 v;
            v.x = acc[i][j + 0] * alpha;
            v.y = acc[i][j + 1] * alpha;
            v.z = acc[i][j + 2] * alpha;
            v.w = acc[i][j + 3] * alpha;
            *reinterpret_cast<float4*>(&C[m * ldc + bn + tx * TN + j]) = v;
        }
    }
}

// ---------------------------------------------------------------------------
// Row softmax (in place, scratch at sOff): one block per 2048-long row.
// ---------------------------------------------------------------------------
__global__ __launch_bounds__(256)
void softmax_kernel(long sOff)
{
    const int N = 2048;
    float* row = g_scratch + sOff + (long)blockIdx.x * N;
    const int tid = threadIdx.x;

    float vals[8];
    float m = -INFINITY;
    #pragma unroll
    for (int i = 0; i < 8; i++) {
        vals[i] = row[tid + i * 256];
        m = fmaxf(m, vals[i]);
    }
    __shared__ float red_max[8];
    __shared__ float red_sum[8];
    #pragma unroll
    for (int o = 16; o; o >>= 1) m = fmaxf(m, __shfl_xor_sync(0xFFFFFFFFu, m, o));
    if ((tid & 31) == 0) red_max[tid >> 5] = m;
    __syncthreads();
    m = red_max[0];
    #pragma unroll
    for (int i = 1; i < 8; i++) m = fmaxf(m, red_max[i]);

    float sum = 0.f;
    #pragma unroll
    for (int i = 0; i < 8; i++) {
        vals[i] = expf(vals[i] - m);
        sum += vals[i];
    }
    #pragma unroll
    for (int o = 16; o; o >>= 1) sum += __shfl_xor_sync(0xFFFFFFFFu, sum, o);
    if ((tid & 31) == 0) red_sum[tid >> 5] = sum;
    __syncthreads();
    sum = 0.f;
    #pragma unroll
    for (int i = 0; i < 8; i++) sum += red_sum[i];

    const float inv = 1.0f / sum;
    #pragma unroll
    for (int i = 0; i < 8; i++) row[tid + i * 256] = vals[i] * inv;
}

// ---------------------------------------------------------------------------
// Head permutation: output row r' pulls q-flat row
//   h = r'&15, b = (r'>>4)&3, vh = r'>>6  ->  perm = b*2048 + h*128 + vh
// (reshape/transpose chain of the reference, verified algebraically)
// ---------------------------------------------------------------------------
__device__ __forceinline__ int perm_row(int r)
{
    const int h  = r & 15;
    const int b  = (r >> 4) & 3;
    const int vh = r >> 6;
    return b * 2048 + h * 128 + vh;
}

// Dense: C[r',e] = sum_d Q[perm(r'), d] * W[e, d] + bias[e]
// M=8192, N=2048, K=2048 (all ld = 2048). Q = scratch at qOff, C = d_out.
__global__ __launch_bounds__(NTHREADS)
void dense_kernel(long qOff, const float* __restrict__ W,
                  const float* __restrict__ bias, float* __restrict__ C)
{
    const int lda = 2048, ldb = 2048, ldc = 2048;
    __shared__ float As[BK][BM];
    __shared__ float Bs[BK][BN];

    const float* Q = g_scratch + qOff;

    const int bm = blockIdx.y * BM;
    const int bn = blockIdx.x * BN;
    const int tid = threadIdx.x;
    const int tx = tid & 15;
    const int ty = tid >> 4;

    float acc[TM][TN] = {};

    for (int k0 = 0; k0 < 2048; k0 += BK) {
        {   // A load with row gather (contiguous in k)
            const int m  = tid >> 1;
            const int k8 = (tid & 1) * 8;
            const int rp = perm_row(bm + m);
            float4 v0 = *reinterpret_cast<const float4*>(
                &Q[(long)rp * lda + k0 + k8]);
            float4 v1 = *reinterpret_cast<const float4*>(
                &Q[(long)rp * lda + k0 + k8 + 4]);
            As[k8 + 0][m] = v0.x; As[k8 + 1][m] = v0.y;
            As[k8 + 2][m] = v0.z; As[k8 + 3][m] = v0.w;
            As[k8 + 4][m] = v1.x; As[k8 + 5][m] = v1.y;
            As[k8 + 6][m] = v1.z; As[k8 + 7][m] = v1.w;
        }
        {   // B = W (N x K), transposed access
            const int n  = tid >> 1;
            const int k8 = (tid & 1) * 8;
            float4 v0 = *reinterpret_cast<const float4*>(
                &W[(long)(bn + n) * ldb + k0 + k8]);
            float4 v1 = *reinterpret_cast<const float4*>(
                &W[(long)(bn + n) * ldb + k0 + k8 + 4]);
            Bs[k8 + 0][n] = v0.x; Bs[k8 + 1][n] = v0.y;
            Bs[k8 + 2][n] = v0.z; Bs[k8 + 3][n] = v0.w;
            Bs[k8 + 4][n] = v1.x; Bs[k8 + 5][n] = v1.y;
            Bs[k8 + 6][n] = v1.z; Bs[k8 + 7][n] = v1.w;
        }
        __syncthreads();
        #pragma unroll
        for (int k = 0; k < BK; k++) {
            float af[TM], bf[TN];
            #pragma unroll
            for (int i = 0; i < TM; i++) af[i] = As[k][ty * TM + i];
            #pragma unroll
            for (int j = 0; j < TN; j++) bf[j] = Bs[k][tx * TN + j];
            #pragma unroll
            for (int i = 0; i < TM; i++)
                #pragma unroll
                for (int j = 0; j < TN; j++)
                    acc[i][j] = fmaf(af[i], bf[j], acc[i][j]);
        }
        __syncthreads();
    }

    #pragma unroll
    for (int i = 0; i < TM; i++) {
        const long m = bm + ty * TM + i;
        #pragma unroll
        for (int j = 0; j < TN; j += 4) {
            const int n = bn + tx * TN + j;
            float4 v;
            v.x = acc[i][j + 0] + bias[n + 0];
            v.y = acc[i][j + 1] + bias[n + 1];
            v.z = acc[i][j + 2] + bias[n + 2];
            v.w = acc[i][j + 3] + bias[n + 3];
            *reinterpret_cast<float4*>(&C[m * ldc + n]) = v;
        }
    }
}

// ---------------------------------------------------------------------------
// Launch: nothing but kernel launches (graph-capture-safe by construction).
// ---------------------------------------------------------------------------
extern "C" void kernel_launch(void* const* d_in, const int* in_sizes, int n_in,
                              void* d_out, int out_size)
{
    const float* x       = (const float*)d_in[0];  // (4,2048,2048)
    const float* w_qk    = (const float*)d_in[1];  // (4096,2048)
    const float* w_dense = (const float*)d_in[2];  // (2048,2048)
    const float* b_dense = (const float*)d_in[3];  // (2048,)
    float* out = (float*)d_out;

    const float scale = (float)(1.0 / sqrt((double)2048 * 2047 / 2.0));

    // 1) kv = x @ w_qk^T : M=8192 N=4096 K=2048
    sgemm_kernel<false, true><<<dim3(4096 / BN, 8192 / BM, 1), NTHREADS>>>(
        x, 0, w_qk, 0, OFF_KV,
        8192, 4096, 2048, 2048, 2048, 4096, 0, 0, 0, 1.0f);

    // 2) s[b] = k0[b]^T @ v[b]^T * scale : batched, M=N=K=2048
    sgemm_kernel<true, true><<<dim3(2048 / BN, 2048 / BM, 4), NTHREADS>>>(
        nullptr, OFF_KV, nullptr, OFF_KV + 2048, OFF_S,
        2048, 2048, 2048, 4096, 4096, 2048,
        (long)2048 * 4096, (long)2048 * 4096, (long)2048 * 2048, scale);

    // 3) softmax rows (in place)
    softmax_kernel<<<8192, 256>>>(OFF_S);

    // 4) q[b] = a[b] @ v[b]
    sgemm_kernel<false, false><<<dim3(2048 / BN, 2048 / BM, 4), NTHREADS>>>(
        nullptr, OFF_S, nullptr, OFF_KV + 2048, OFF_Q,
        2048, 2048, 2048, 2048, 4096, 2048,
        (long)2048 * 2048, (long)2048 * 4096, (long)2048 * 2048, 1.0f);

    // 5) out = gather_perm(q) @ w_dense^T + b_dense
    dense_kernel<<<dim3(2048 / BN, 8192 / BM, 1), NTHREADS>>>(
        OFF_Q, w_dense, b_dense, out);
}

// round 7
// speedup vs baseline: 3.5394x; 3.5394x over previous
#include <cuda_runtime.h>
#include <math.h>
#include <stdint.h>

// ---------------------------------------------------------------------------
// SelfAttention_39676907883685  (B=4, T=2048, D=2048, HEADS=16)
// TF32 mma.sync (sm_80-class PTX — the only tensor path this toolchain
// compiles for target sm_103; tcgen05 is 'a'-gated and rejected by ptxas).
//
//   kv  = x @ w_qk^T                      (8192 x 4096)
//   s[b]= k0[b]^T @ v[b]^T * scale        (4 x 2048 x 2048)
//   a   = softmax(s)                      (rows of 2048)
//   q[b]= a[b] @ v[b]                     (4 x 2048 x 2048)
//   out = gather_perm(q) @ w_dense^T + b  (8192 x 2048)
//
// One GEMM template, D[m,n] = alpha * sum_k opA[m,k]*opB[n,k] (+bias):
//   CTA tile 128x128, BK=32, 8 warps (warp tile 64x32), m16n8k8 tf32,
//   3-stage cp.async pipeline, conflict-free padded SMEM.
// ---------------------------------------------------------------------------

#define OFF_KV 0L
#define OFF_S  33554432L
#define OFF_Q  50331648L
__device__ float g_scratch[67108864];   // 268 MB scratch

__device__ __forceinline__ uint32_t smem_u32(const void* p) {
    uint32_t a;
    asm("{ .reg .u64 t; cvta.to.shared.u64 t, %1; cvt.u32.u64 %0, t; }"
        : "=r"(a) : "l"(p));
    return a;
}
__device__ __forceinline__ uint32_t tf32r(float x) {   // round-to-nearest tf32
    uint32_t u;
    asm("cvt.rna.tf32.f32 %0, %1;" : "=r"(u) : "f"(x));
    return u;
}
__device__ __forceinline__ void cp16(uint32_t dst, const void* src) {
    asm volatile("cp.async.cg.shared.global [%0], [%1], 16;"
                 :: "r"(dst), "l"(src) : "memory");
}
__device__ __forceinline__ void mma8(float* d, const uint32_t* a, const uint32_t* b) {
    asm volatile(
        "mma.sync.aligned.m16n8k8.row.col.f32.tf32.tf32.f32 "
        "{%0,%1,%2,%3}, {%4,%5,%6,%7}, {%8,%9}, {%0,%1,%2,%3};"
        : "+f"(d[0]), "+f"(d[1]), "+f"(d[2]), "+f"(d[3])
        : "r"(a[0]), "r"(a[1]), "r"(a[2]), "r"(a[3]), "r"(b[0]), "r"(b[1]));
}

// Head permutation (validated in round 3 at rel_err 1.5e-6)
__device__ __forceinline__ int perm_row(int r)
{
    const int h  = r & 15;
    const int b  = (r >> 4) & 3;
    const int vh = r >> 6;
    return b * 2048 + h * 128 + vh;
}

// ---------------------------------------------------------------------------
// TRA/TRB: operand source is k-major (rows = k, cols = m/n) -> load into a
// k-major padded tile; otherwise m/n-major padded tile. GATHER: permute A
// rows (dense-layer input). BIAS: add bias[n] in epilogue.
// ---------------------------------------------------------------------------
template<bool TRA, bool TRB, bool GATHER, bool BIAS>
__global__ __launch_bounds__(256)
void mma_gemm(const float* __restrict__ Aext, long aOff,
              const float* __restrict__ Bext, long bOff,
              float* __restrict__ Cext, long cOff,
              int K, int lda, int ldb, int ldc,
              long sA, long sB, long sC, float alpha,
              const float* __restrict__ bias)
{
    constexpr int AST = TRA ? 136 : 36;           // floats per smem row
    constexpr int BST = TRB ? 136 : 36;
    constexpr int ASZ = TRA ? 32 * 136 : 128 * 36; // floats per tile
    constexpr int BSZ = TRB ? 32 * 136 : 128 * 36;
    constexpr int STG = ASZ + BSZ;                 // floats per stage

    extern __shared__ float sm[];

    const int tid  = threadIdx.x;
    const int lane = tid & 31;
    const int wid  = tid >> 5;
    const int wm   = (wid >> 2) * 64;   // warp m-offset (0/64)
    const int wn   = (wid & 3) * 32;    // warp n-offset (0/32/64/96)
    const int r    = lane >> 2;         // fragment row group 0..7
    const int c    = lane & 3;          // fragment col group 0..3

    const float* A = (Aext ? Aext : g_scratch + aOff) + (long)blockIdx.z * sA;
    const float* B = (Bext ? Bext : g_scratch + bOff) + (long)blockIdx.z * sB;
    float*       C = (Cext ? Cext : g_scratch + cOff) + (long)blockIdx.z * sC;

    const int bm = blockIdx.y * 128;
    const int bn = blockIdx.x * 128;
    const uint32_t smb = smem_u32(sm);

    float acc[4][4][4] = {};

    // ---- async stage loader: global -> smem slot (cidx % 3) ----
    auto load_stage = [&](int cidx) {
        const int slot = cidx % 3;
        const int k0 = cidx << 5;
        const uint32_t ab = smb + (uint32_t)(slot * STG) * 4u;
        #pragma unroll
        for (int t = 0; t < 4; t++) {
            const int idx = tid + t * 256;
            if (!TRA) {
                const int row = idx >> 3, c4 = (idx & 7) * 4;
                const int gr = GATHER ? perm_row(bm + row) : (bm + row);
                cp16(ab + (uint32_t)(row * AST + c4) * 4u,
                     A + (long)gr * lda + k0 + c4);
            } else {
                const int kk = idx >> 5, c4 = (idx & 31) * 4;
                cp16(ab + (uint32_t)(kk * AST + c4) * 4u,
                     A + (long)(k0 + kk) * lda + bm + c4);
            }
        }
        const uint32_t bb = ab + (uint32_t)ASZ * 4u;
        #pragma unroll
        for (int t = 0; t < 4; t++) {
            const int idx = tid + t * 256;
            if (!TRB) {
                const int row = idx >> 3, c4 = (idx & 7) * 4;
                cp16(bb + (uint32_t)(row * BST + c4) * 4u,
                     B + (long)(bn + row) * ldb + k0 + c4);
            } else {
                const int kk = idx >> 5, c4 = (idx & 31) * 4;
                cp16(bb + (uint32_t)(kk * BST + c4) * 4u,
                     B + (long)(k0 + kk) * ldb + bn + c4);
            }
        }
    };

    const int KCH = K >> 5;   // chunks of 32

    load_stage(0);
    asm volatile("cp.async.commit_group;" ::: "memory");
    load_stage(1);
    asm volatile("cp.async.commit_group;" ::: "memory");

    for (int cc = 0; cc < KCH; cc++) {
        if (cc + 2 < KCH) load_stage(cc + 2);
        asm volatile("cp.async.commit_group;" ::: "memory");
        asm volatile("cp.async.wait_group 2;" ::: "memory");
        __syncthreads();

        const float* As = sm + (cc % 3) * STG;
        const float* Bs = As + ASZ;

        #pragma unroll
        for (int s = 0; s < 4; s++) {       // 4 x k8 steps per 32-chunk
            uint32_t af[4][4], bf[4][2];
            #pragma unroll
            for (int mt = 0; mt < 4; mt++) {
                const int m0 = wm + mt * 16;
                if (!TRA) {
                    const float* p = As + (m0 + r) * AST + s * 8 + c;
                    af[mt][0] = tf32r(p[0]);
                    af[mt][1] = tf32r(p[8 * AST]);
                    af[mt][2] = tf32r(p[4]);
                    af[mt][3] = tf32r(p[8 * AST + 4]);
                } else {
                    const float* p = As + (s * 8 + c) * AST + m0 + r;
                    af[mt][0] = tf32r(p[0]);
                    af[mt][1] = tf32r(p[8]);
                    af[mt][2] = tf32r(p[4 * AST]);
                    af[mt][3] = tf32r(p[4 * AST + 8]);
                }
            }
            #pragma unroll
            for (int nt = 0; nt < 4; nt++) {
                const int n0 = wn + nt * 8;
                if (!TRB) {
                    const float* p = Bs + (n0 + r) * BST + s * 8 + c;
                    bf[nt][0] = tf32r(p[0]);
                    bf[nt][1] = tf32r(p[4]);
                } else {
                    const float* p = Bs + (s * 8 + c) * BST + n0 + r;
                    bf[nt][0] = tf32r(p[0]);
                    bf[nt][1] = tf32r(p[4 * BST]);
                }
            }
            #pragma unroll
            for (int mt = 0; mt < 4; mt++)
                #pragma unroll
                for (int nt = 0; nt < 4; nt++)
                    mma8(acc[mt][nt], af[mt], bf[nt]);
        }
        __syncthreads();
    }

    // ---- epilogue ----
    #pragma unroll
    for (int mt = 0; mt < 4; mt++) {
        const long row0 = bm + wm + mt * 16 + r;
        #pragma unroll
        for (int nt = 0; nt < 4; nt++) {
            const int col = bn + wn + nt * 8 + c * 2;
            float bx = 0.f, by = 0.f;
            if (BIAS) { bx = bias[col]; by = bias[col + 1]; }
            float2 v0, v1;
            v0.x = acc[mt][nt][0] * alpha + bx;
            v0.y = acc[mt][nt][1] * alpha + by;
            v1.x = acc[mt][nt][2] * alpha + bx;
            v1.y = acc[mt][nt][3] * alpha + by;
            *reinterpret_cast<float2*>(C + row0 * ldc + col)       = v0;
            *reinterpret_cast<float2*>(C + (row0 + 8) * ldc + col) = v1;
        }
    }
}

// ---------------------------------------------------------------------------
// Row softmax (in place): one block per 2048-long row.
// ---------------------------------------------------------------------------
__global__ __launch_bounds__(256)
void softmax_kernel(long sOff)
{
    const int N = 2048;
    float* row = g_scratch + sOff + (long)blockIdx.x * N;
    const int tid = threadIdx.x;

    float vals[8];
    float m = -INFINITY;
    #pragma unroll
    for (int i = 0; i < 8; i++) {
        vals[i] = row[tid + i * 256];
        m = fmaxf(m, vals[i]);
    }
    __shared__ float red_max[8];
    __shared__ float red_sum[8];
    #pragma unroll
    for (int o = 16; o; o >>= 1) m = fmaxf(m, __shfl_xor_sync(0xFFFFFFFFu, m, o));
    if ((tid & 31) == 0) red_max[tid >> 5] = m;
    __syncthreads();
    m = red_max[0];
    #pragma unroll
    for (int i = 1; i < 8; i++) m = fmaxf(m, red_max[i]);

    float sum = 0.f;
    #pragma unroll
    for (int i = 0; i < 8; i++) {
        vals[i] = expf(vals[i] - m);
        sum += vals[i];
    }
    #pragma unroll
    for (int o = 16; o; o >>= 1) sum += __shfl_xor_sync(0xFFFFFFFFu, sum, o);
    if ((tid & 31) == 0) red_sum[tid >> 5] = sum;
    __syncthreads();
    sum = 0.f;
    #pragma unroll
    for (int i = 0; i < 8; i++) sum += red_sum[i];

    const float inv = 1.0f / sum;
    #pragma unroll
    for (int i = 0; i < 8; i++) row[tid + i * 256] = vals[i] * inv;
}

// ---------------------------------------------------------------------------
// Launch (kernel launches + idempotent attribute sets only)
// ---------------------------------------------------------------------------
extern "C" void kernel_launch(void* const* d_in, const int* in_sizes, int n_in,
                              void* d_out, int out_size)
{
    const float* x       = (const float*)d_in[0];  // (4,2048,2048)
    const float* w_qk    = (const float*)d_in[1];  // (4096,2048)
    const float* w_dense = (const float*)d_in[2];  // (2048,2048)
    const float* b_dense = (const float*)d_in[3];  // (2048,)
    float* out = (float*)d_out;

    const float scale = (float)(1.0 / sqrt((double)2048 * 2047 / 2.0));

    // dynamic smem per instantiation: 3 stages * (ASZ+BSZ) floats
    const int smem_nn = 3 * (128 * 36 + 128 * 36) * 4;   // 110592
    const int smem_tn = 3 * (32 * 136 + 128 * 36) * 4;   // 107520
    const int smem_nt = smem_tn;

    cudaFuncSetAttribute(mma_gemm<false,false,false,false>,
                         cudaFuncAttributeMaxDynamicSharedMemorySize, smem_nn);
    cudaFuncSetAttribute(mma_gemm<true,false,false,false>,
                         cudaFuncAttributeMaxDynamicSharedMemorySize, smem_tn);
    cudaFuncSetAttribute(mma_gemm<false,true,false,false>,
                         cudaFuncAttributeMaxDynamicSharedMemorySize, smem_nt);
    cudaFuncSetAttribute(mma_gemm<false,false,true,true>,
                         cudaFuncAttributeMaxDynamicSharedMemorySize, smem_nn);

    // 1) kv = x @ w_qk^T : M=8192 N=4096 K=2048
    mma_gemm<false,false,false,false><<<dim3(32, 64, 1), 256, smem_nn>>>(
        x, 0, w_qk, 0, nullptr, OFF_KV,
        2048, 2048, 2048, 4096, 0, 0, 0, 1.0f, nullptr);

    // 2) s[b][i][j] = sum_m kv[b*2048+m, i] * kv[b*2048+j, 2048+m] * scale
    //    A k-major (TRA, lda=4096), B natural (ldb=4096, base col 2048)
    mma_gemm<true,false,false,false><<<dim3(16, 16, 4), 256, smem_tn>>>(
        nullptr, OFF_KV, nullptr, OFF_KV + 2048, nullptr, OFF_S,
        2048, 4096, 4096, 2048,
        (long)2048 * 4096, (long)2048 * 4096, (long)2048 * 2048, scale, nullptr);

    // 3) softmax rows (in place)
    softmax_kernel<<<8192, 256>>>(OFF_S);

    // 4) q[b][i][d] = sum_t a[b,i,t] * kv[b*2048+t, 2048+d]
    //    A natural (lda=2048), B k-major (TRB, ldb=4096, base col 2048)
    mma_gemm<false,true,false,false><<<dim3(16, 16, 4), 256, smem_nt>>>(
        nullptr, OFF_S, nullptr, OFF_KV + 2048, nullptr, OFF_Q,
        2048, 2048, 4096, 2048,
        (long)2048 * 2048, (long)2048 * 4096, (long)2048 * 2048, 1.0f, nullptr);

    // 5) out = gather_perm(q) @ w_dense^T + b_dense
    mma_gemm<false,false,true,true><<<dim3(16, 64, 1), 256, smem_nn>>>(
        nullptr, OFF_Q, w_dense, 0, out, 0,
        2048, 2048, 2048, 2048, 0, 0, 0, 1.0f, b_dense);
}

// round 9
// speedup vs baseline: 3.7731x; 1.0660x over previous
#include <cuda_runtime.h>
#include <math.h>
#include <stdint.h>

// ---------------------------------------------------------------------------
// SelfAttention_39676907883685  (B=4, T=2048, D=2048, HEADS=16)
// TF32 mma.sync tensor path (sm_103-safe PTX).
//
//   kv  = x @ w_qk^T                      (8192 x 4096)
//   s[b]= k0[b]^T @ v[b]^T * scale        (4 x 2048 x 2048)
//   a   = softmax(s)                      (rows of 2048)
//   q[b]= a[b] @ v[b]                     (4 x 2048 x 2048)
//   out = gather_perm(q) @ w_dense^T + b  (8192 x 2048)
//
// All GEMM operands in memory are pre-rounded to tf32 (inputs via a copy
// kernel; intermediates via epilogue/softmax rounding), so the GEMM inner
// loop feeds raw bits to mma.sync — no cvt in the hot path.
// ---------------------------------------------------------------------------

#define OFF_KV  0L
#define OFF_S   33554432L
#define OFF_Q   50331648L
#define OFF_XR  67108864L
#define OFF_WQK 83886080L
#define OFF_WD  92274688L
__device__ float g_scratch[96468992];   // 386 MB scratch

__device__ __forceinline__ uint32_t smem_u32(const void* p) {
    uint32_t a;
    asm("{ .reg .u64 t; cvta.to.shared.u64 t, %1; cvt.u32.u64 %0, t; }"
        : "=r"(a) : "l"(p));
    return a;
}
__device__ __forceinline__ uint32_t tf32r(float x) {   // round-to-nearest tf32
    uint32_t u;
    asm("cvt.rna.tf32.f32 %0, %1;" : "=r"(u) : "f"(x));
    return u;
}
__device__ __forceinline__ float tf32f(float x) {
    return __uint_as_float(tf32r(x));
}
__device__ __forceinline__ void cp16(uint32_t dst, const void* src) {
    asm volatile("cp.async.cg.shared.global [%0], [%1], 16;"
                 :: "r"(dst), "l"(src) : "memory");
}
__device__ __forceinline__ void mma8(float* d, const uint32_t* a, const uint32_t* b) {
    asm volatile(
        "mma.sync.aligned.m16n8k8.row.col.f32.tf32.tf32.f32 "
        "{%0,%1,%2,%3}, {%4,%5,%6,%7}, {%8,%9}, {%0,%1,%2,%3};"
        : "+f"(d[0]), "+f"(d[1]), "+f"(d[2]), "+f"(d[3])
        : "r"(a[0]), "r"(a[1]), "r"(a[2]), "r"(a[3]), "r"(b[0]), "r"(b[1]));
}

// Head permutation (validated: rel_err 1.5e-6 in fp32 round)
__device__ __forceinline__ int perm_row(int r)
{
    const int h  = r & 15;
    const int b  = (r >> 4) & 3;
    const int vh = r >> 6;
    return b * 2048 + h * 128 + vh;
}

// ---------------------------------------------------------------------------
// Elementwise tf32 rounding copy: src (external) -> g_scratch + dstOff
// ---------------------------------------------------------------------------
__global__ __launch_bounds__(256)
void round_copy(const float* __restrict__ src, long dstOff, int n4)
{
    const int i = blockIdx.x * blockDim.x + threadIdx.x;
    if (i < n4) {
        float4 v = reinterpret_cast<const float4*>(src)[i];
        v.x = tf32f(v.x); v.y = tf32f(v.y);
        v.z = tf32f(v.z); v.w = tf32f(v.w);
        reinterpret_cast<float4*>(g_scratch + dstOff)[i] = v;
    }
}

// ---------------------------------------------------------------------------
// TF32 GEMM: D[m,n] = alpha * sum_k opA[m,k]*opB[n,k] (+bias)
// TRA/TRB: operand stored k-major. GATHER: permute A rows. BIAS: +bias[n].
// ROUND: round output to tf32 (it feeds a later GEMM).
// CTA 128x128, BK=32, 8 warps (64x32 each), 3-stage cp.async pipeline.
// ---------------------------------------------------------------------------
template<bool TRA, bool TRB, bool GATHER, bool BIAS, bool ROUND>
__global__ __launch_bounds__(256, 2)
void mma_gemm(const float* __restrict__ Aext, long aOff,
              const float* __restrict__ Bext, long bOff,
              float* __restrict__ Cext, long cOff,
              int K, int lda, int ldb, int ldc,
              long sA, long sB, long sC, float alpha,
              const float* __restrict__ bias)
{
    constexpr int AST = TRA ? 136 : 36;            // floats per smem row
    constexpr int BST = TRB ? 136 : 36;
    constexpr int ASZ = TRA ? 32 * 136 : 128 * 36; // floats per tile
    constexpr int BSZ = TRB ? 32 * 136 : 128 * 36;
    constexpr int STG = ASZ + BSZ;

    extern __shared__ float sm[];

    const int tid  = threadIdx.x;
    const int lane = tid & 31;
    const int wid  = tid >> 5;
    const int wm   = (wid >> 2) * 64;
    const int wn   = (wid & 3) * 32;
    const int r    = lane >> 2;
    const int c    = lane & 3;

    const float* A = (Aext ? Aext : g_scratch + aOff) + (long)blockIdx.z * sA;
    const float* B = (Bext ? Bext : g_scratch + bOff) + (long)blockIdx.z * sB;
    float*       C = (Cext ? Cext : g_scratch + cOff) + (long)blockIdx.z * sC;

    const int bm = blockIdx.y * 128;
    const int bn = blockIdx.x * 128;
    const uint32_t smb = smem_u32(sm);

    // ---- precompute per-thread cp.async source pointers & smem offsets ----
    const float* gA[4]; uint32_t offA[4];
    const float* gB[4]; uint32_t offB[4];
    #pragma unroll
    for (int t = 0; t < 4; t++) {
        const int idx = tid + t * 256;
        if (!TRA) {
            const int row = idx >> 3, c4 = (idx & 7) * 4;
            const int gr = GATHER ? perm_row(bm + row) : (bm + row);
            gA[t]  = A + (long)gr * lda + c4;
            offA[t] = (uint32_t)(row * AST + c4) * 4u;
        } else {
            const int kk = idx >> 5, c4 = (idx & 31) * 4;
            gA[t]  = A + (long)kk * lda + bm + c4;
            offA[t] = (uint32_t)(kk * AST + c4) * 4u;
        }
        if (!TRB) {
            const int row = idx >> 3, c4 = (idx & 7) * 4;
            gB[t]  = B + (long)(bn + row) * ldb + c4;
            offB[t] = (uint32_t)(row * BST + c4) * 4u;
        } else {
            const int kk = idx >> 5, c4 = (idx & 31) * 4;
            gB[t]  = B + (long)kk * ldb + bn + c4;
            offB[t] = (uint32_t)(kk * BST + c4) * 4u;
        }
    }
    const long advA = TRA ? (long)32 * lda : 32;
    const long advB = TRB ? (long)32 * ldb : 32;

    float acc[4][4][4] = {};

    int pslot = 0;
    auto load_stage = [&]() {
        const uint32_t ab = smb + (uint32_t)(pslot * STG) * 4u;
        const uint32_t bb = ab + (uint32_t)ASZ * 4u;
        #pragma unroll
        for (int t = 0; t < 4; t++) { cp16(ab + offA[t], gA[t]); gA[t] += advA; }
        #pragma unroll
        for (int t = 0; t < 4; t++) { cp16(bb + offB[t], gB[t]); gB[t] += advB; }
        pslot = (pslot == 2) ? 0 : pslot + 1;
    };

    const int KCH = K >> 5;

    load_stage();
    asm volatile("cp.async.commit_group;" ::: "memory");
    load_stage();
    asm volatile("cp.async.commit_group;" ::: "memory");

    int cslot = 0;
    for (int cc = 0; cc < KCH; cc++) {
        if (cc + 2 < KCH) load_stage();
        asm volatile("cp.async.commit_group;" ::: "memory");
        asm volatile("cp.async.wait_group 2;" ::: "memory");
        __syncthreads();

        const float* As = sm + cslot * STG;
        const float* Bs = As + ASZ;
        cslot = (cslot == 2) ? 0 : cslot + 1;

        // fragment base pointers (constant offsets from these below)
        const float* aBase = !TRA ? (As + (wm + r) * AST + c)
                                  : (As + c * AST + wm + r);
        const float* bBase = !TRB ? (Bs + (wn + r) * BST + c)
                                  : (Bs + c * BST + wn + r);

        #pragma unroll
        for (int s = 0; s < 4; s++) {       // 4 x k8 steps per 32-chunk
            uint32_t af[4][4], bf[4][2];
            #pragma unroll
            for (int mt = 0; mt < 4; mt++) {
                if (!TRA) {
                    const float* p = aBase + mt * 16 * AST + s * 8;
                    af[mt][0] = __float_as_uint(p[0]);
                    af[mt][1] = __float_as_uint(p[8 * AST]);
                    af[mt][2] = __float_as_uint(p[4]);
                    af[mt][3] = __float_as_uint(p[8 * AST + 4]);
                } else {
                    const float* p = aBase + s * 8 * AST + mt * 16;
                    af[mt][0] = __float_as_uint(p[0]);
                    af[mt][1] = __float_as_uint(p[8]);
                    af[mt][2] = __float_as_uint(p[4 * AST]);
                    af[mt][3] = __float_as_uint(p[4 * AST + 8]);
                }
            }
            #pragma unroll
            for (int nt = 0; nt < 4; nt++) {
                if (!TRB) {
                    const float* p = bBase + nt * 8 * BST + s * 8;
                    bf[nt][0] = __float_as_uint(p[0]);
                    bf[nt][1] = __float_as_uint(p[4]);
                } else {
                    const float* p = bBase + s * 8 * BST + nt * 8;
                    bf[nt][0] = __float_as_uint(p[0]);
                    bf[nt][1] = __float_as_uint(p[4 * BST]);
                }
            }
            #pragma unroll
            for (int mt = 0; mt < 4; mt++)
                #pragma unroll
                for (int nt = 0; nt < 4; nt++)
                    mma8(acc[mt][nt], af[mt], bf[nt]);
        }
        __syncthreads();
    }

    // ---- epilogue ----
    #pragma unroll
    for (int mt = 0; mt < 4; mt++) {
        const long row0 = bm + wm + mt * 16 + r;
        #pragma unroll
        for (int nt = 0; nt < 4; nt++) {
            const int col = bn + wn + nt * 8 + c * 2;
            float bx = 0.f, by = 0.f;
            if (BIAS) { bx = bias[col]; by = bias[col + 1]; }
            float2 v0, v1;
            v0.x = acc[mt][nt][0] * alpha + bx;
            v0.y = acc[mt][nt][1] * alpha + by;
            v1.x = acc[mt][nt][2] * alpha + bx;
            v1.y = acc[mt][nt][3] * alpha + by;
            if (ROUND) {
                v0.x = tf32f(v0.x); v0.y = tf32f(v0.y);
                v1.x = tf32f(v1.x); v1.y = tf32f(v1.y);
            }
            *reinterpret_cast<float2*>(C + row0 * ldc + col)       = v0;
            *reinterpret_cast<float2*>(C + (row0 + 8) * ldc + col) = v1;
        }
    }
}

// ---------------------------------------------------------------------------
// Row softmax (in place, writes tf32-rounded probabilities)
// ---------------------------------------------------------------------------
__global__ __launch_bounds__(256)
void softmax_kernel(long sOff)
{
    const int N = 2048;
    float* row = g_scratch + sOff + (long)blockIdx.x * N;
    const int tid = threadIdx.x;

    float vals[8];
    float m = -INFINITY;
    #pragma unroll
    for (int i = 0; i < 8; i++) {
        vals[i] = row[tid + i * 256];
        m = fmaxf(m, vals[i]);
    }
    __shared__ float red_max[8];
    __shared__ float red_sum[8];
    #pragma unroll
    for (int o = 16; o; o >>= 1) m = fmaxf(m, __shfl_xor_sync(0xFFFFFFFFu, m, o));
    if ((tid & 31) == 0) red_max[tid >> 5] = m;
    __syncthreads();
    m = red_max[0];
    #pragma unroll
    for (int i = 1; i < 8; i++) m = fmaxf(m, red_max[i]);

    float sum = 0.f;
    #pragma unroll
    for (int i = 0; i < 8; i++) {
        vals[i] = expf(vals[i] - m);
        sum += vals[i];
    }
    #pragma unroll
    for (int o = 16; o; o >>= 1) sum += __shfl_xor_sync(0xFFFFFFFFu, sum, o);
    if ((tid & 31) == 0) red_sum[tid >> 5] = sum;
    __syncthreads();
    sum = 0.f;
    #pragma unroll
    for (int i = 0; i < 8; i++) sum += red_sum[i];

    const float inv = 1.0f / sum;
    #pragma unroll
    for (int i = 0; i < 8; i++) row[tid + i * 256] = tf32f(vals[i] * inv);
}

// ---------------------------------------------------------------------------
// Launch
// ---------------------------------------------------------------------------
extern "C" void kernel_launch(void* const* d_in, const int* in_sizes, int n_in,
                              void* d_out, int out_size)
{
    const float* x       = (const float*)d_in[0];  // (4,2048,2048)
    const float* w_qk    = (const float*)d_in[1];  // (4096,2048)
    const float* w_dense = (const float*)d_in[2];  // (2048,2048)
    const float* b_dense = (const float*)d_in[3];  // (2048,)
    float* out = (float*)d_out;

    const float scale = (float)(1.0 / sqrt((double)2048 * 2047 / 2.0));

    const int smem_nn = 3 * (128 * 36 + 128 * 36) * 4;   // 110592
    const int smem_tn = 3 * (32 * 136 + 128 * 36) * 4;   // 107520

    cudaFuncSetAttribute(mma_gemm<false,false,false,false,true>,
                         cudaFuncAttributeMaxDynamicSharedMemorySize, smem_nn);
    cudaFuncSetAttribute(mma_gemm<true,false,false,false,true>,
                         cudaFuncAttributeMaxDynamicSharedMemorySize, smem_tn);
    cudaFuncSetAttribute(mma_gemm<false,true,false,false,true>,
                         cudaFuncAttributeMaxDynamicSharedMemorySize, smem_tn);
    cudaFuncSetAttribute(mma_gemm<false,false,true,true,false>,
                         cudaFuncAttributeMaxDynamicSharedMemorySize, smem_nn);

    // 0) pre-round inputs to tf32 (copies in scratch)
    round_copy<<<16384, 256>>>(x,       OFF_XR,  4194304);
    round_copy<<<8192,  256>>>(w_qk,    OFF_WQK, 2097152);
    round_copy<<<4096,  256>>>(w_dense, OFF_WD,  1048576);

    // 1) kv = xr @ w_qkr^T : M=8192 N=4096 K=2048 (output rounded)
    mma_gemm<false,false,false,false,true><<<dim3(32, 64, 1), 256, smem_nn>>>(
        nullptr, OFF_XR, nullptr, OFF_WQK, nullptr, OFF_KV,
        2048, 2048, 2048, 4096, 0, 0, 0, 1.0f, nullptr);

    // 2) s[b][i][j] = sum_m kv[b*2048+m, i] * kv[b*2048+j, 2048+m] * scale
    mma_gemm<true,false,false,false,true><<<dim3(16, 16, 4), 256, smem_tn>>>(
        nullptr, OFF_KV, nullptr, OFF_KV + 2048, nullptr, OFF_S,
        2048, 4096, 4096, 2048,
        (long)2048 * 4096, (long)2048 * 4096, (long)2048 * 2048, scale, nullptr);

    // 3) softmax rows (in place, rounded)
    softmax_kernel<<<8192, 256>>>(OFF_S);

    // 4) q[b][i][d] = sum_t a[b,i,t] * kv[b*2048+t, 2048+d]  (output rounded)
    mma_gemm<false,true,false,false,true><<<dim3(16, 16, 4), 256, smem_tn>>>(
        nullptr, OFF_S, nullptr, OFF_KV + 2048, nullptr, OFF_Q,
        2048, 2048, 4096, 2048,
        (long)2048 * 2048, (long)2048 * 4096, (long)2048 * 2048, 1.0f, nullptr);

    // 5) out = gather_perm(q) @ w_denser^T + b_dense
    mma_gemm<false,false,true,true,false><<<dim3(16, 64, 1), 256, smem_nn>>>(
        nullptr, OFF_Q, nullptr, OFF_WD, out, 0,
        2048, 2048, 2048, 2048, 0, 0, 0, 1.0f, b_dense);
}

// round 10
// speedup vs baseline: 3.8640x; 1.0241x over previous
#include <cuda_runtime.h>
#include <math.h>
#include <stdint.h>

// ---------------------------------------------------------------------------
// SelfAttention_39676907883685  (B=4, T=2048, D=2048, HEADS=16)
// TF32 mma.sync tensor path (sm_103-safe PTX).
//
//   kv  = x @ w_qk^T                      (8192 x 4096)
//   s[b]= k0[b]^T @ v[b]^T * scale        (4 x 2048 x 2048)
//   a   = softmax(s)                      (rows of 2048)
//   q[b]= a[b] @ v[b]                     (4 x 2048 x 2048)
//   out = gather_perm(q) @ w_dense^T + b  (8192 x 2048)
//
// All GEMM operands in memory are pre-rounded to tf32, so the GEMM inner
// loop feeds raw bits to mma.sync — no cvt in the hot path.
// Multistage pipeline with ONE __syncthreads per k-chunk.
// ---------------------------------------------------------------------------

#define OFF_KV  0L
#define OFF_S   33554432L
#define OFF_Q   50331648L
#define OFF_XR  67108864L
#define OFF_WQK 83886080L
#define OFF_WD  92274688L
__device__ float g_scratch[96468992];   // 386 MB scratch

__device__ __forceinline__ uint32_t smem_u32(const void* p) {
    uint32_t a;
    asm("{ .reg .u64 t; cvta.to.shared.u64 t, %1; cvt.u32.u64 %0, t; }"
        : "=r"(a) : "l"(p));
    return a;
}
__device__ __forceinline__ uint32_t tf32r(float x) {   // round-to-nearest tf32
    uint32_t u;
    asm("cvt.rna.tf32.f32 %0, %1;" : "=r"(u) : "f"(x));
    return u;
}
__device__ __forceinline__ float tf32f(float x) {
    return __uint_as_float(tf32r(x));
}
__device__ __forceinline__ void cp16(uint32_t dst, const void* src) {
    asm volatile("cp.async.cg.shared.global [%0], [%1], 16;"
                 :: "r"(dst), "l"(src) : "memory");
}
__device__ __forceinline__ void mma8(float* d, const uint32_t* a, const uint32_t* b) {
    asm volatile(
        "mma.sync.aligned.m16n8k8.row.col.f32.tf32.tf32.f32 "
        "{%0,%1,%2,%3}, {%4,%5,%6,%7}, {%8,%9}, {%0,%1,%2,%3};"
        : "+f"(d[0]), "+f"(d[1]), "+f"(d[2]), "+f"(d[3])
        : "r"(a[0]), "r"(a[1]), "r"(a[2]), "r"(a[3]), "r"(b[0]), "r"(b[1]));
}

// Head permutation (validated: rel_err 1.5e-6 in fp32 round)
__device__ __forceinline__ int perm_row(int r)
{
    const int h  = r & 15;
    const int b  = (r >> 4) & 3;
    const int vh = r >> 6;
    return b * 2048 + h * 128 + vh;
}

// ---------------------------------------------------------------------------
// Elementwise tf32 rounding copy: src (external) -> g_scratch + dstOff
// ---------------------------------------------------------------------------
__global__ __launch_bounds__(256)
void round_copy(const float* __restrict__ src, long dstOff, int n4)
{
    const int i = blockIdx.x * blockDim.x + threadIdx.x;
    if (i < n4) {
        float4 v = reinterpret_cast<const float4*>(src)[i];
        v.x = tf32f(v.x); v.y = tf32f(v.y);
        v.z = tf32f(v.z); v.w = tf32f(v.w);
        reinterpret_cast<float4*>(g_scratch + dstOff)[i] = v;
    }
}

// ---------------------------------------------------------------------------
// TF32 GEMM: D[m,n] = alpha * sum_k opA[m,k]*opB[n,k] (+bias)
// TRA/TRB: operand stored k-major. GATHER: permute A rows. BIAS: +bias[n].
// ROUND: round output to tf32 (it feeds a later GEMM).
// CTA 128x128, BK=32, 8 warps (64x32 each), 3-stage cp.async pipeline,
// one __syncthreads per chunk.
// ---------------------------------------------------------------------------
template<bool TRA, bool TRB, bool GATHER, bool BIAS, bool ROUND>
__global__ __launch_bounds__(256, 2)
void mma_gemm(const float* __restrict__ Aext, long aOff,
              const float* __restrict__ Bext, long bOff,
              float* __restrict__ Cext, long cOff,
              int K, int lda, int ldb, int ldc,
              long sA, long sB, long sC, float alpha,
              const float* __restrict__ bias)
{
    constexpr int AST = TRA ? 136 : 36;            // floats per smem row
    constexpr int BST = TRB ? 136 : 36;
    constexpr int ASZ = TRA ? 32 * 136 : 128 * 36; // floats per tile
    constexpr int BSZ = TRB ? 32 * 136 : 128 * 36;
    constexpr int STG = ASZ + BSZ;

    extern __shared__ float sm[];

    const int tid  = threadIdx.x;
    const int lane = tid & 31;
    const int wid  = tid >> 5;
    const int wm   = (wid >> 2) * 64;
    const int wn   = (wid & 3) * 32;
    const int r    = lane >> 2;
    const int c    = lane & 3;

    const float* A = (Aext ? Aext : g_scratch + aOff) + (long)blockIdx.z * sA;
    const float* B = (Bext ? Bext : g_scratch + bOff) + (long)blockIdx.z * sB;
    float*       C = (Cext ? Cext : g_scratch + cOff) + (long)blockIdx.z * sC;

    const int bm = blockIdx.y * 128;
    const int bn = blockIdx.x * 128;
    const uint32_t smb = smem_u32(sm);

    // ---- precompute per-thread cp.async source pointers & smem offsets ----
    const float* gA[4]; uint32_t offA[4];
    const float* gB[4]; uint32_t offB[4];
    #pragma unroll
    for (int t = 0; t < 4; t++) {
        const int idx = tid + t * 256;
        if (!TRA) {
            const int row = idx >> 3, c4 = (idx & 7) * 4;
            const int gr = GATHER ? perm_row(bm + row) : (bm + row);
            gA[t]  = A + (long)gr * lda + c4;
            offA[t] = (uint32_t)(row * AST + c4) * 4u;
        } else {
            const int kk = idx >> 5, c4 = (idx & 31) * 4;
            gA[t]  = A + (long)kk * lda + bm + c4;
            offA[t] = (uint32_t)(kk * AST + c4) * 4u;
        }
        if (!TRB) {
            const int row = idx >> 3, c4 = (idx & 7) * 4;
            gB[t]  = B + (long)(bn + row) * ldb + c4;
            offB[t] = (uint32_t)(row * BST + c4) * 4u;
        } else {
            const int kk = idx >> 5, c4 = (idx & 31) * 4;
            gB[t]  = B + (long)kk * ldb + bn + c4;
            offB[t] = (uint32_t)(kk * BST + c4) * 4u;
        }
    }
    const long advA = TRA ? (long)32 * lda : 32;
    const long advB = TRB ? (long)32 * ldb : 32;

    float acc[4][4][4] = {};

    int pslot = 0;
    auto load_stage = [&]() {
        const uint32_t ab = smb + (uint32_t)(pslot * STG) * 4u;
        const uint32_t bb = ab + (uint32_t)ASZ * 4u;
        #pragma unroll
        for (int t = 0; t < 4; t++) { cp16(ab + offA[t], gA[t]); gA[t] += advA; }
        #pragma unroll
        for (int t = 0; t < 4; t++) { cp16(bb + offB[t], gB[t]); gB[t] += advB; }
        pslot = (pslot == 2) ? 0 : pslot + 1;
    };

    const int KCH = K >> 5;

    load_stage();
    asm volatile("cp.async.commit_group;" ::: "memory");
    load_stage();
    asm volatile("cp.async.commit_group;" ::: "memory");

    int cslot = 0;
    for (int cc = 0; cc < KCH; cc++) {
        // group cc must be complete (pending <= 1 leaves only group cc+1)
        asm volatile("cp.async.wait_group 1;" ::: "memory");
        __syncthreads();
        // issue loads for chunk cc+2 into slot (cc+2)%3 — that slot was last
        // read at iteration cc-1, which every warp finished before the sync.
        if (cc + 2 < KCH) load_stage();
        asm volatile("cp.async.commit_group;" ::: "memory");

        const float* As = sm + cslot * STG;
        const float* Bs = As + ASZ;
        cslot = (cslot == 2) ? 0 : cslot + 1;

        const float* aBase = !TRA ? (As + (wm + r) * AST + c)
                                  : (As + c * AST + wm + r);
        const float* bBase = !TRB ? (Bs + (wn + r) * BST + c)
                                  : (Bs + c * BST + wn + r);

        #pragma unroll
        for (int s = 0; s < 4; s++) {       // 4 x k8 steps per 32-chunk
            uint32_t af[4][4], bf[4][2];
            #pragma unroll
            for (int mt = 0; mt < 4; mt++) {
                if (!TRA) {
                    const float* p = aBase + mt * 16 * AST + s * 8;
                    af[mt][0] = __float_as_uint(p[0]);
                    af[mt][1] = __float_as_uint(p[8 * AST]);
                    af[mt][2] = __float_as_uint(p[4]);
                    af[mt][3] = __float_as_uint(p[8 * AST + 4]);
                } else {
                    const float* p = aBase + s * 8 * AST + mt * 16;
                    af[mt][0] = __float_as_uint(p[0]);
                    af[mt][1] = __float_as_uint(p[8]);
                    af[mt][2] = __float_as_uint(p[4 * AST]);
                    af[mt][3] = __float_as_uint(p[4 * AST + 8]);
                }
            }
            #pragma unroll
            for (int nt = 0; nt < 4; nt++) {
                if (!TRB) {
                    const float* p = bBase + nt * 8 * BST + s * 8;
                    bf[nt][0] = __float_as_uint(p[0]);
                    bf[nt][1] = __float_as_uint(p[4]);
                } else {
                    const float* p = bBase + s * 8 * BST + nt * 8;
                    bf[nt][0] = __float_as_uint(p[0]);
                    bf[nt][1] = __float_as_uint(p[4 * BST]);
                }
            }
            #pragma unroll
            for (int mt = 0; mt < 4; mt++)
                #pragma unroll
                for (int nt = 0; nt < 4; nt++)
                    mma8(acc[mt][nt], af[mt], bf[nt]);
        }
    }

    // ---- epilogue ----
    #pragma unroll
    for (int mt = 0; mt < 4; mt++) {
        const long row0 = bm + wm + mt * 16 + r;
        #pragma unroll
        for (int nt = 0; nt < 4; nt++) {
            const int col = bn + wn + nt * 8 + c * 2;
            float bx = 0.f, by = 0.f;
            if (BIAS) { bx = bias[col]; by = bias[col + 1]; }
            float2 v0, v1;
            v0.x = acc[mt][nt][0] * alpha + bx;
            v0.y = acc[mt][nt][1] * alpha + by;
            v1.x = acc[mt][nt][2] * alpha + bx;
            v1.y = acc[mt][nt][3] * alpha + by;
            if (ROUND) {
                v0.x = tf32f(v0.x); v0.y = tf32f(v0.y);
                v1.x = tf32f(v1.x); v1.y = tf32f(v1.y);
            }
            *reinterpret_cast<float2*>(C + row0 * ldc + col)       = v0;
            *reinterpret_cast<float2*>(C + (row0 + 8) * ldc + col) = v1;
        }
    }
}

// ---------------------------------------------------------------------------
// Row softmax (in place, writes tf32-rounded probabilities)
// ---------------------------------------------------------------------------
__global__ __launch_bounds__(256)
void softmax_kernel(long sOff)
{
    const int N = 2048;
    float* row = g_scratch + sOff + (long)blockIdx.x * N;
    const int tid = threadIdx.x;

    float vals[8];
    float m = -INFINITY;
    #pragma unroll
    for (int i = 0; i < 8; i++) {
        vals[i] = row[tid + i * 256];
        m = fmaxf(m, vals[i]);
    }
    __shared__ float red_max[8];
    __shared__ float red_sum[8];
    #pragma unroll
    for (int o = 16; o; o >>= 1) m = fmaxf(m, __shfl_xor_sync(0xFFFFFFFFu, m, o));
    if ((tid & 31) == 0) red_max[tid >> 5] = m;
    __syncthreads();
    m = red_max[0];
    #pragma unroll
    for (int i = 1; i < 8; i++) m = fmaxf(m, red_max[i]);

    float sum = 0.f;
    #pragma unroll
    for (int i = 0; i < 8; i++) {
        vals[i] = expf(vals[i] - m);
        sum += vals[i];
    }
    #pragma unroll
    for (int o = 16; o; o >>= 1) sum += __shfl_xor_sync(0xFFFFFFFFu, sum, o);
    if ((tid & 31) == 0) red_sum[tid >> 5] = sum;
    __syncthreads();
    sum = 0.f;
    #pragma unroll
    for (int i = 0; i < 8; i++) sum += red_sum[i];

    const float inv = 1.0f / sum;
    #pragma unroll
    for (int i = 0; i < 8; i++) row[tid + i * 256] = tf32f(vals[i] * inv);
}

// ---------------------------------------------------------------------------
// Launch
// ---------------------------------------------------------------------------
extern "C" void kernel_launch(void* const* d_in, const int* in_sizes, int n_in,
                              void* d_out, int out_size)
{
    const float* x       = (const float*)d_in[0];  // (4,2048,2048)
    const float* w_qk    = (const float*)d_in[1];  // (4096,2048)
    const float* w_dense = (const float*)d_in[2];  // (2048,2048)
    const float* b_dense = (const float*)d_in[3];  // (2048,)
    float* out = (float*)d_out;

    const float scale = (float)(1.0 / sqrt((double)2048 * 2047 / 2.0));

    const int smem_nn = 3 * (128 * 36 + 128 * 36) * 4;   // 110592
    const int smem_tn = 3 * (32 * 136 + 128 * 36) * 4;   // 107520

    cudaFuncSetAttribute(mma_gemm<false,false,false,false,true>,
                         cudaFuncAttributeMaxDynamicSharedMemorySize, smem_nn);
    cudaFuncSetAttribute(mma_gemm<true,false,false,false,true>,
                         cudaFuncAttributeMaxDynamicSharedMemorySize, smem_tn);
    cudaFuncSetAttribute(mma_gemm<false,true,false,false,true>,
                         cudaFuncAttributeMaxDynamicSharedMemorySize, smem_tn);
    cudaFuncSetAttribute(mma_gemm<false,false,true,true,false>,
                         cudaFuncAttributeMaxDynamicSharedMemorySize, smem_nn);

    // 0) pre-round inputs to tf32 (copies in scratch)
    round_copy<<<16384, 256>>>(x,       OFF_XR,  4194304);
    round_copy<<<8192,  256>>>(w_qk,    OFF_WQK, 2097152);
    round_copy<<<4096,  256>>>(w_dense, OFF_WD,  1048576);

    // 1) kv = xr @ w_qkr^T : M=8192 N=4096 K=2048 (output rounded)
    mma_gemm<false,false,false,false,true><<<dim3(32, 64, 1), 256, smem_nn>>>(
        nullptr, OFF_XR, nullptr, OFF_WQK, nullptr, OFF_KV,
        2048, 2048, 2048, 4096, 0, 0, 0, 1.0f, nullptr);

    // 2) s[b][i][j] = sum_m kv[b*2048+m, i] * kv[b*2048+j, 2048+m] * scale
    mma_gemm<true,false,false,false,true><<<dim3(16, 16, 4), 256, smem_tn>>>(
        nullptr, OFF_KV, nullptr, OFF_KV + 2048, nullptr, OFF_S,
        2048, 4096, 4096, 2048,
        (long)2048 * 4096, (long)2048 * 4096, (long)2048 * 2048, scale, nullptr);

    // 3) softmax rows (in place, rounded)
    softmax_kernel<<<8192, 256>>>(OFF_S);

    // 4) q[b][i][d] = sum_t a[b,i,t] * kv[b*2048+t, 2048+d]  (output rounded)
    mma_gemm<false,true,false,false,true><<<dim3(16, 16, 4), 256, smem_tn>>>(
        nullptr, OFF_S, nullptr, OFF_KV + 2048, nullptr, OFF_Q,
        2048, 2048, 4096, 2048,
        (long)2048 * 2048, (long)2048 * 4096, (long)2048 * 2048, 1.0f, nullptr);

    // 5) out = gather_perm(q) @ w_denser^T + b_dense
    mma_gemm<false,false,true,true,false><<<dim3(16, 64, 1), 256, smem_nn>>>(
        nullptr, OFF_Q, nullptr, OFF_WD, out, 0,
        2048, 2048, 2048, 2048, 0, 0, 0, 1.0f, b_dense);
}

// round 12
// speedup vs baseline: 3.9356x; 1.0185x over previous
#include <cuda_runtime.h>
#include <math.h>
#include <stdint.h>

// ---------------------------------------------------------------------------
// SelfAttention_39676907883685  (B=4, T=2048, D=2048, HEADS=16)
// TF32 mma.sync tensor path (sm_103-safe PTX).
//
//   kv  = x @ w_qk^T                      (8192 x 4096)
//   s[b]= k0[b]^T @ v[b]^T * scale        (4 x 2048 x 2048)
//   a   = softmax(s)                      (rows of 2048)
//   q[b]= a[b] @ v[b]                     (4 x 2048 x 2048)
//   out = gather_perm(q) @ w_dense^T + b  (8192 x 2048)
//
// CTA 128x128, 4 warps, warp tile 64x64 (1.0 LDS per MMA — smem-port
// pressure halved vs 64x32). 3-stage cp.async pipeline, one sync/chunk.
// All operands pre-rounded to tf32; no cvt in the hot path.
// ---------------------------------------------------------------------------

#define OFF_KV  0L
#define OFF_S   33554432L
#define OFF_Q   50331648L
#define OFF_XR  67108864L
#define OFF_WQK 83886080L
#define OFF_WD  92274688L
__device__ float g_scratch[96468992];   // 386 MB scratch

__device__ __forceinline__ uint32_t smem_u32(const void* p) {
    uint32_t a;
    asm("{ .reg .u64 t; cvta.to.shared.u64 t, %1; cvt.u32.u64 %0, t; }"
        : "=r"(a) : "l"(p));
    return a;
}
__device__ __forceinline__ uint32_t tf32r(float x) {
    uint32_t u;
    asm("cvt.rna.tf32.f32 %0, %1;" : "=r"(u) : "f"(x));
    return u;
}
__device__ __forceinline__ float tf32f(float x) {
    return __uint_as_float(tf32r(x));
}
__device__ __forceinline__ void cp16(uint32_t dst, const void* src) {
    asm volatile("cp.async.cg.shared.global [%0], [%1], 16;"
                 :: "r"(dst), "l"(src) : "memory");
}
__device__ __forceinline__ void mma8(float* d, const uint32_t* a, const uint32_t* b) {
    asm volatile(
        "mma.sync.aligned.m16n8k8.row.col.f32.tf32.tf32.f32 "
        "{%0,%1,%2,%3}, {%4,%5,%6,%7}, {%8,%9}, {%0,%1,%2,%3};"
        : "+f"(d[0]), "+f"(d[1]), "+f"(d[2]), "+f"(d[3])
        : "r"(a[0]), "r"(a[1]), "r"(a[2]), "r"(a[3]), "r"(b[0]), "r"(b[1]));
}

// Head permutation (validated: rel_err 1.5e-6 in fp32 round)
__device__ __forceinline__ int perm_row(int r)
{
    const int h  = r & 15;
    const int b  = (r >> 4) & 3;
    const int vh = r >> 6;
    return b * 2048 + h * 128 + vh;
}

// ---------------------------------------------------------------------------
// Elementwise tf32 rounding copy: src (external) -> g_scratch + dstOff
// ---------------------------------------------------------------------------
__global__ __launch_bounds__(256)
void round_copy(const float* __restrict__ src, long dstOff, int n4)
{
    const int i = blockIdx.x * blockDim.x + threadIdx.x;
    if (i < n4) {
        float4 v = reinterpret_cast<const float4*>(src)[i];
        v.x = tf32f(v.x); v.y = tf32f(v.y);
        v.z = tf32f(v.z); v.w = tf32f(v.w);
        reinterpret_cast<float4*>(g_scratch + dstOff)[i] = v;
    }
}

// ---------------------------------------------------------------------------
// TF32 GEMM: D[m,n] = alpha * sum_k opA[m,k]*opB[n,k] (+bias)
// TRA/TRB: operand stored k-major. GATHER: permute A rows. BIAS: +bias[n].
// ROUND: round output to tf32.
// CTA 128x128, 4 warps (64x64 each), BK=32, 3-stage pipeline.
// ---------------------------------------------------------------------------
template<bool TRA, bool TRB, bool GATHER, bool BIAS, bool ROUND>
__global__ __launch_bounds__(128, 2)
void mma_gemm(const float* __restrict__ Aext, long aOff,
              const float* __restrict__ Bext, long bOff,
              float* __restrict__ Cext, long cOff,
              int K, int lda, int ldb, int ldc,
              long sA, long sB, long sC, float alpha,
              const float* __restrict__ bias)
{
    constexpr int AST = TRA ? 136 : 36;            // floats per smem row
    constexpr int BST = TRB ? 136 : 36;
    constexpr int ASZ = TRA ? 32 * 136 : 128 * 36; // floats per tile
    constexpr int BSZ = TRB ? 32 * 136 : 128 * 36;
    constexpr int STG = ASZ + BSZ;
    // smem byte-offset step between the 8 per-thread load units of a tile
    constexpr uint32_t stpAoff = (TRA ? 4 * 136 : 16 * 36) * 4u;
    constexpr uint32_t stpBoff = (TRB ? 4 * 136 : 16 * 36) * 4u;

    extern __shared__ float sm[];

    const int tid  = threadIdx.x;
    const int lane = tid & 31;
    const int wid  = tid >> 5;          // 0..3
    const int wm   = (wid >> 1) * 64;
    const int wn   = (wid & 1) * 64;
    const int r    = lane >> 2;
    const int c    = lane & 3;

    const float* A = (Aext ? Aext : g_scratch + aOff) + (long)blockIdx.z * sA;
    const float* B = (Bext ? Bext : g_scratch + bOff) + (long)blockIdx.z * sB;
    float*       C = (Cext ? Cext : g_scratch + cOff) + (long)blockIdx.z * sC;

    const int bm = blockIdx.y * 128;
    const int bn = blockIdx.x * 128;
    const uint32_t smb = smem_u32(sm);

    // ---- loader state (affine in t except GATHER-A which needs 8 ptrs) ----
    const float* gA0 = nullptr; const float* gAg[8];
    const float* gB0;
    uint32_t offA0, offB0;
    long stepA, stepB;

    if (!TRA) {
        const int row = tid >> 3, c4 = (tid & 7) * 4;     // row 0..15
        if (GATHER) {
            #pragma unroll
            for (int t = 0; t < 8; t++)
                gAg[t] = A + (long)perm_row(bm + row + t * 16) * lda + c4;
        } else {
            gA0 = A + (long)(bm + row) * lda + c4;
        }
        stepA = (long)16 * lda;
        offA0 = (uint32_t)(row * AST + c4) * 4u;
    } else {
        const int kk = tid >> 5, c4 = (tid & 31) * 4;     // kk 0..3
        gA0 = A + (long)kk * lda + bm + c4;
        stepA = (long)4 * lda;
        offA0 = (uint32_t)(kk * AST + c4) * 4u;
    }
    if (!TRB) {
        const int row = tid >> 3, c4 = (tid & 7) * 4;
        gB0 = B + (long)(bn + row) * ldb + c4;
        stepB = (long)16 * ldb;
        offB0 = (uint32_t)(row * BST + c4) * 4u;
    } else {
        const int kk = tid >> 5, c4 = (tid & 31) * 4;
        gB0 = B + (long)kk * ldb + bn + c4;
        stepB = (long)4 * ldb;
        offB0 = (uint32_t)(kk * BST + c4) * 4u;
    }
    const long advA = TRA ? (long)32 * lda : 32;
    const long advB = TRB ? (long)32 * ldb : 32;

    float acc[4][8][4] = {};

    int pslot = 0;
    auto load_stage = [&]() {
        const uint32_t ab = smb + (uint32_t)(pslot * STG) * 4u;
        const uint32_t bb = ab + (uint32_t)ASZ * 4u;
        if (GATHER && !TRA) {
            #pragma unroll
            for (int t = 0; t < 8; t++) {
                cp16(ab + offA0 + t * stpAoff, gAg[t]);
                gAg[t] += advA;
            }
        } else {
            const float* p = gA0;
            #pragma unroll
            for (int t = 0; t < 8; t++) { cp16(ab + offA0 + t * stpAoff, p); p += stepA; }
            gA0 += advA;
        }
        {
            const float* p = gB0;
            #pragma unroll
            for (int t = 0; t < 8; t++) { cp16(bb + offB0 + t * stpBoff, p); p += stepB; }
            gB0 += advB;
        }
        pslot = (pslot == 2) ? 0 : pslot + 1;
    };

    const int KCH = K >> 5;

    load_stage();
    asm volatile("cp.async.commit_group;" ::: "memory");
    load_stage();
    asm volatile("cp.async.commit_group;" ::: "memory");

    int cslot = 0;
    for (int cc = 0; cc < KCH; cc++) {
        asm volatile("cp.async.wait_group 1;" ::: "memory");
        __syncthreads();
        if (cc + 2 < KCH) load_stage();
        asm volatile("cp.async.commit_group;" ::: "memory");

        const float* As = sm + cslot * STG;
        const float* Bs = As + ASZ;
        cslot = (cslot == 2) ? 0 : cslot + 1;

        const float* aBase = !TRA ? (As + (wm + r) * AST + c)
                                  : (As + c * AST + wm + r);
        const float* bBase = !TRB ? (Bs + (wn + r) * BST + c)
                                  : (Bs + c * BST + wn + r);

        #pragma unroll
        for (int s = 0; s < 4; s++) {       // 4 x k8 steps per 32-chunk
            uint32_t af[4][4], bf[8][2];
            #pragma unroll
            for (int mt = 0; mt < 4; mt++) {
                if (!TRA) {
                    const float* p = aBase + mt * 16 * AST + s * 8;
                    af[mt][0] = __float_as_uint(p[0]);
                    af[mt][1] = __float_as_uint(p[8 * AST]);
                    af[mt][2] = __float_as_uint(p[4]);
                    af[mt][3] = __float_as_uint(p[8 * AST + 4]);
                } else {
                    const float* p = aBase + s * 8 * AST + mt * 16;
                    af[mt][0] = __float_as_uint(p[0]);
                    af[mt][1] = __float_as_uint(p[8]);
                    af[mt][2] = __float_as_uint(p[4 * AST]);
                    af[mt][3] = __float_as_uint(p[4 * AST + 8]);
                }
            }
            #pragma unroll
            for (int nt = 0; nt < 8; nt++) {
                if (!TRB) {
                    const float* p = bBase + nt * 8 * BST + s * 8;
                    bf[nt][0] = __float_as_uint(p[0]);
                    bf[nt][1] = __float_as_uint(p[4]);
                } else {
                    const float* p = bBase + s * 8 * BST + nt * 8;
                    bf[nt][0] = __float_as_uint(p[0]);
                    bf[nt][1] = __float_as_uint(p[4 * BST]);
                }
            }
            #pragma unroll
            for (int mt = 0; mt < 4; mt++)
                #pragma unroll
                for (int nt = 0; nt < 8; nt++)
                    mma8(acc[mt][nt], af[mt], bf[nt]);
        }
    }

    // ---- epilogue ----
    #pragma unroll
    for (int mt = 0; mt < 4; mt++) {
        const long row0 = bm + wm + mt * 16 + r;
        #pragma unroll
        for (int nt = 0; nt < 8; nt++) {
            const int col = bn + wn + nt * 8 + c * 2;
            float bx = 0.f, by = 0.f;
            if (BIAS) { bx = bias[col]; by = bias[col + 1]; }
            float2 v0, v1;
            v0.x = acc[mt][nt][0] * alpha + bx;
            v0.y = acc[mt][nt][1] * alpha + by;
            v1.x = acc[mt][nt][2] * alpha + bx;
            v1.y = acc[mt][nt][3] * alpha + by;
            if (ROUND) {
                v0.x = tf32f(v0.x); v0.y = tf32f(v0.y);
                v1.x = tf32f(v1.x); v1.y = tf32f(v1.y);
            }
            *reinterpret_cast<float2*>(C + row0 * ldc + col)       = v0;
            *reinterpret_cast<float2*>(C + (row0 + 8) * ldc + col) = v1;
        }
    }
}

// ---------------------------------------------------------------------------
// Row softmax (in place, writes tf32-rounded probabilities)
// ---------------------------------------------------------------------------
__global__ __launch_bounds__(256)
void softmax_kernel(long sOff)
{
    const int N = 2048;
    float* row = g_scratch + sOff + (long)blockIdx.x * N;
    const int tid = threadIdx.x;

    float vals[8];
    float m = -INFINITY;
    #pragma unroll
    for (int i = 0; i < 8; i++) {
        vals[i] = row[tid + i * 256];
        m = fmaxf(m, vals[i]);
    }
    __shared__ float red_max[8];
    __shared__ float red_sum[8];
    #pragma unroll
    for (int o = 16; o; o >>= 1) m = fmaxf(m, __shfl_xor_sync(0xFFFFFFFFu, m, o));
    if ((tid & 31) == 0) red_max[tid >> 5] = m;
    __syncthreads();
    m = red_max[0];
    #pragma unroll
    for (int i = 1; i < 8; i++) m = fmaxf(m, red_max[i]);

    float sum = 0.f;
    #pragma unroll
    for (int i = 0; i < 8; i++) {
        vals[i] = expf(vals[i] - m);
        sum += vals[i];
    }
    #pragma unroll
    for (int o = 16; o; o >>= 1) sum += __shfl_xor_sync(0xFFFFFFFFu, sum, o);
    if ((tid & 31) == 0) red_sum[tid >> 5] = sum;
    __syncthreads();
    sum = 0.f;
    #pragma unroll
    for (int i = 0; i < 8; i++) sum += red_sum[i];

    const float inv = 1.0f / sum;
    #pragma unroll
    for (int i = 0; i < 8; i++) row[tid + i * 256] = tf32f(vals[i] * inv);
}

// ---------------------------------------------------------------------------
// Launch
// ---------------------------------------------------------------------------
extern "C" void kernel_launch(void* const* d_in, const int* in_sizes, int n_in,
                              void* d_out, int out_size)
{
    const float* x       = (const float*)d_in[0];  // (4,2048,2048)
    const float* w_qk    = (const float*)d_in[1];  // (4096,2048)
    const float* w_dense = (const float*)d_in[2];  // (2048,2048)
    const float* b_dense = (const float*)d_in[3];  // (2048,)
    float* out = (float*)d_out;

    const float scale = (float)(1.0 / sqrt((double)2048 * 2047 / 2.0));

    const int smem_nn = 3 * (128 * 36 + 128 * 36) * 4;   // 110592
    const int smem_tn = 3 * (32 * 136 + 128 * 36) * 4;   // 107520

    cudaFuncSetAttribute(mma_gemm<false,false,false,false,true>,
                         cudaFuncAttributeMaxDynamicSharedMemorySize, smem_nn);
    cudaFuncSetAttribute(mma_gemm<true,false,false,false,true>,
                         cudaFuncAttributeMaxDynamicSharedMemorySize, smem_tn);
    cudaFuncSetAttribute(mma_gemm<false,true,false,false,true>,
                         cudaFuncAttributeMaxDynamicSharedMemorySize, smem_tn);
    cudaFuncSetAttribute(mma_gemm<false,false,true,true,false>,
                         cudaFuncAttributeMaxDynamicSharedMemorySize, smem_nn);

    // 0) pre-round inputs to tf32 (copies in scratch)
    round_copy<<<16384, 256>>>(x,       OFF_XR,  4194304);
    round_copy<<<8192,  256>>>(w_qk,    OFF_WQK, 2097152);
    round_copy<<<4096,  256>>>(w_dense, OFF_WD,  1048576);

    // 1) kv = xr @ w_qkr^T : M=8192 N=4096 K=2048 (output rounded)
    mma_gemm<false,false,false,false,true><<<dim3(32, 64, 1), 128, smem_nn>>>(
        nullptr, OFF_XR, nullptr, OFF_WQK, nullptr, OFF_KV,
        2048, 2048, 2048, 4096, 0, 0, 0, 1.0f, nullptr);

    // 2) s[b][i][j] = sum_m kv[b*2048+m, i] * kv[b*2048+j, 2048+m] * scale
    mma_gemm<true,false,false,false,true><<<dim3(16, 16, 4), 128, smem_tn>>>(
        nullptr, OFF_KV, nullptr, OFF_KV + 2048, nullptr, OFF_S,
        2048, 4096, 4096, 2048,
        (long)2048 * 4096, (long)2048 * 4096, (long)2048 * 2048, scale, nullptr);

    // 3) softmax rows (in place, rounded)
    softmax_kernel<<<8192, 256>>>(OFF_S);

    // 4) q[b][i][d] = sum_t a[b,i,t] * kv[b*2048+t, 2048+d]  (output rounded)
    mma_gemm<false,true,false,false,true><<<dim3(16, 16, 4), 128, smem_tn>>>(
        nullptr, OFF_S, nullptr, OFF_KV + 2048, nullptr, OFF_Q,
        2048, 2048, 4096, 2048,
        (long)2048 * 2048, (long)2048 * 4096, (long)2048 * 2048, 1.0f, nullptr);

    // 5) out = gather_perm(q) @ w_denser^T + b_dense
    mma_gemm<false,false,true,true,false><<<dim3(16, 64, 1), 128, smem_nn>>>(
        nullptr, OFF_Q, nullptr, OFF_WD, out, 0,
        2048, 2048, 2048, 2048, 0, 0, 0, 1.0f, b_dense);
}

// round 17
// speedup vs baseline: 7.2100x; 1.8320x over previous
#include <cuda_runtime.h>
#include <cuda_fp16.h>
#include <math.h>
#include <stdint.h>

// ---------------------------------------------------------------------------
// SelfAttention_39676907883685  (B=4, T=2048, D=2048, HEADS=16)
// FP16 mma.sync path: fp16 mantissa (11 bit) == tf32 mantissa, but
// m16n8k16 f16 HMMA runs at full tensor rate (tf32 is half-rate).
//
//   kvh  = xh @ wqkh^T                      (8192 x 4096)   fp16
//   k0T/vT = transpose slices of kvh        (per batch)     fp16
//   s[b] = k0T[b] @ v[b](rows) * scale      (4 x 2048^2)    fp16
//   a    = softmax(s)                                       fp16
//   q[b] = a[b] @ vT[b]^T(rows)             (4 x 2048^2)    fp16
//   out  = gather_perm(q) @ wdh^T + b       (8192 x 2048)   fp32
//
// Single NN GEMM template (A m-major, B n-major, both k-contiguous):
// CTA 128x128, 4 warps (64x64), BK=64 halves, 3-stage cp.async, 1 sync/chunk.
// ---------------------------------------------------------------------------

// scratch carved in HALF units
#define H_KVH  0L
#define H_K0T  33554432L
#define H_VT   50331648L
#define H_SH   67108864L
#define H_QH   83886080L
#define H_XH   100663296L
#define H_WQKH 117440512L
#define H_WDH  125829120L
__device__ float g_scratch[67108864];   // 256 MB (used as half[134M])

__device__ __forceinline__ uint32_t smem_u32(const void* p) {
    uint32_t a;
    asm("{ .reg .u64 t; cvta.to.shared.u64 t, %1; cvt.u32.u64 %0, t; }"
        : "=r"(a) : "l"(p));
    return a;
}
__device__ __forceinline__ void cp16(uint32_t dst, const void* src) {
    asm volatile("cp.async.cg.shared.global [%0], [%1], 16;"
                 :: "r"(dst), "l"(src) : "memory");
}
__device__ __forceinline__ void mma16(float* d, const uint32_t* a, const uint32_t* b) {
    asm volatile(
        "mma.sync.aligned.m16n8k16.row.col.f32.f16.f16.f32 "
        "{%0,%1,%2,%3}, {%4,%5,%6,%7}, {%8,%9}, {%0,%1,%2,%3};"
        : "+f"(d[0]), "+f"(d[1]), "+f"(d[2]), "+f"(d[3])
        : "r"(a[0]), "r"(a[1]), "r"(a[2]), "r"(a[3]), "r"(b[0]), "r"(b[1]));
}

// Head permutation (validated in round 3)
__device__ __forceinline__ int perm_row(int r)
{
    const int h  = r & 15;
    const int b  = (r >> 4) & 3;
    const int vh = r >> 6;
    return b * 2048 + h * 128 + vh;
}

// ---------------------------------------------------------------------------
// fp16 rounding copy: 8 floats per thread -> 8 halves
// ---------------------------------------------------------------------------
__global__ __launch_bounds__(256)
void round_copy_h(const float* __restrict__ src, long dstOffH, int n8)
{
    const int i = blockIdx.x * blockDim.x + threadIdx.x;
    if (i < n8) {
        const float4 v0 = reinterpret_cast<const float4*>(src)[i * 2];
        const float4 v1 = reinterpret_cast<const float4*>(src)[i * 2 + 1];
        __half2 h[4];
        h[0] = __floats2half2_rn(v0.x, v0.y);
        h[1] = __floats2half2_rn(v0.z, v0.w);
        h[2] = __floats2half2_rn(v1.x, v1.y);
        h[3] = __floats2half2_rn(v1.z, v1.w);
        *reinterpret_cast<uint4*>((__half*)g_scratch + dstOffH + (long)i * 8) =
            *reinterpret_cast<uint4*>(h);
    }
}

// ---------------------------------------------------------------------------
// Transpose kvh slices: z = b*2 + tgt. tgt0: k0T[b][i][m] = kvh[b*2048+m][i]
//                                     tgt1: vT [b][d][t] = kvh[b*2048+t][2048+d]
// 64x64 half tiles, 256 threads.
// ---------------------------------------------------------------------------
__global__ __launch_bounds__(256)
void transpose_kv()
{
    __shared__ __half ts[64 * 72];
    const __half* kvh = (const __half*)g_scratch + H_KVH;
    const int b   = blockIdx.z >> 1;
    const int tgt = blockIdx.z & 1;
    const long srcCol = tgt ? 2048 : 0;
    __half* dst = (__half*)g_scratch + (tgt ? H_VT : H_K0T) + (long)b * 2048 * 2048;

    const int mt = blockIdx.x * 64;   // source row tile
    const int it = blockIdx.y * 64;   // source col tile
    const int u   = threadIdx.x & 7;
    const int row = threadIdx.x >> 3;  // 0..31

    #pragma unroll
    for (int p = 0; p < 2; p++) {
        const int m = row + p * 32;
        const uint4 v = *reinterpret_cast<const uint4*>(
            kvh + (long)(b * 2048 + mt + m) * 4096 + srcCol + it + u * 8);
        *reinterpret_cast<uint4*>(ts + m * 72 + u * 8) = v;
    }
    __syncthreads();
    #pragma unroll
    for (int p = 0; p < 2; p++) {
        const int i = row + p * 32;
        __half tmp[8];
        #pragma unroll
        for (int j = 0; j < 8; j++) tmp[j] = ts[(u * 8 + j) * 72 + i];
        *reinterpret_cast<uint4*>(dst + (long)(it + i) * 2048 + mt + u * 8) =
            *reinterpret_cast<uint4*>(tmp);
    }
}

// ---------------------------------------------------------------------------
// FP16 NN GEMM: D[m,n] = alpha * sum_k A[m,k]*B[n,k] (+bias)
// A: m-major lda halves; B: n-major ldb halves; both k-contiguous.
// GATHER: permute A rows. HALF_OUT: fp16 out to scratch; else fp32 to Cext.
// CTA 128x128, 4 warps 64x64, BK=64 halves, 3-stage pipeline.
// ---------------------------------------------------------------------------
template<bool GATHER, bool BIAS, bool HALF_OUT>
__global__ __launch_bounds__(128, 2)
void hgemm(long aOffH, long bOffH, float* __restrict__ CextF, long cOffH,
           int K, int lda, int ldb, int ldc,
           long sA, long sB, long sC, float alpha,
           const float* __restrict__ bias)
{
    constexpr int ST  = 72;          // halves per smem row (64 + 8 pad)
    constexpr int TSZ = 128 * ST;    // halves per tile
    constexpr int STG = 2 * TSZ;     // halves per stage

    extern __shared__ __half smh[];

    const int tid  = threadIdx.x;
    const int lane = tid & 31;
    const int wid  = tid >> 5;          // 0..3
    const int wm   = (wid >> 1) * 64;
    const int wn   = (wid & 1) * 64;
    const int r    = lane >> 2;
    const int c    = lane & 3;

    const __half* A = (const __half*)g_scratch + aOffH + (long)blockIdx.z * sA;
    const __half* B = (const __half*)g_scratch + bOffH + (long)blockIdx.z * sB;

    const int bm = blockIdx.y * 128;
    const int bn = blockIdx.x * 128;
    const uint32_t smb = smem_u32(smh);

    // ---- loader: per thread 8x 16B units per tile; rows r0+16t, unit u ----
    const int u  = tid & 7;
    const int r0 = tid >> 3;            // 0..15
    const uint32_t offA0 = (uint32_t)(r0 * ST + u * 8) * 2u;  // bytes
    const uint32_t stp   = (uint32_t)(16 * ST) * 2u;          // bytes per 16 rows

    const __half* gA0 = nullptr; const __half* gAg[8];
    if (GATHER) {
        #pragma unroll
        for (int t = 0; t < 8; t++)
            gAg[t] = A + (long)perm_row(bm + r0 + 16 * t) * lda + u * 8;
    } else {
        gA0 = A + (long)(bm + r0) * lda + u * 8;
    }
    const __half* gB0 = B + (long)(bn + r0) * ldb + u * 8;
    const long stepA = (long)16 * lda;
    const long stepB = (long)16 * ldb;

    float acc[4][8][4] = {};

    int pslot = 0;
    auto load_stage = [&]() {
        const uint32_t ab = smb + (uint32_t)(pslot * STG) * 2u;
        const uint32_t bb = ab + (uint32_t)TSZ * 2u;
        if (GATHER) {
            #pragma unroll
            for (int t = 0; t < 8; t++) {
                cp16(ab + offA0 + t * stp, gAg[t]);
                gAg[t] += 64;
            }
        } else {
            const __half* p = gA0;
            #pragma unroll
            for (int t = 0; t < 8; t++) { cp16(ab + offA0 + t * stp, p); p += stepA; }
            gA0 += 64;
        }
        {
            const __half* p = gB0;
            #pragma unroll
            for (int t = 0; t < 8; t++) { cp16(bb + offA0 + t * stp, p); p += stepB; }
            gB0 += 64;
        }
        pslot = (pslot == 2) ? 0 : pslot + 1;
    };

    const int KCH = K >> 6;     // chunks of 64 halves

    load_stage();
    asm volatile("cp.async.commit_group;" ::: "memory");
    load_stage();
    asm volatile("cp.async.commit_group;" ::: "memory");

    int cslot = 0;
    for (int cc = 0; cc < KCH; cc++) {
        asm volatile("cp.async.wait_group 1;" ::: "memory");
        __syncthreads();
        if (cc + 2 < KCH) load_stage();
        asm volatile("cp.async.commit_group;" ::: "memory");

        const __half* As = smh + cslot * STG;
        const __half* Bs = As + TSZ;
        cslot = (cslot == 2) ? 0 : cslot + 1;

        const __half* aBase = As + (wm + r) * ST + 2 * c;
        const __half* bBase = Bs + (wn + r) * ST + 2 * c;

        #pragma unroll
        for (int s = 0; s < 4; s++) {       // 4 x k16 steps per 64-chunk
            uint32_t af[4][4], bf[8][2];
            #pragma unroll
            for (int mt = 0; mt < 4; mt++) {
                const __half* p = aBase + mt * 16 * ST + s * 16;
                af[mt][0] = *reinterpret_cast<const uint32_t*>(p);
                af[mt][1] = *reinterpret_cast<const uint32_t*>(p + 8 * ST);
                af[mt][2] = *reinterpret_cast<const uint32_t*>(p + 8);
                af[mt][3] = *reinterpret_cast<const uint32_t*>(p + 8 * ST + 8);
            }
            #pragma unroll
            for (int nt = 0; nt < 8; nt++) {
                const __half* p = bBase + nt * 8 * ST + s * 16;
                bf[nt][0] = *reinterpret_cast<const uint32_t*>(p);
                bf[nt][1] = *reinterpret_cast<const uint32_t*>(p + 8);
            }
            #pragma unroll
            for (int mt = 0; mt < 4; mt++)
                #pragma unroll
                for (int nt = 0; nt < 8; nt++)
                    mma16(acc[mt][nt], af[mt], bf[nt]);
        }
    }

    // ---- epilogue ----
    if (HALF_OUT) {
        __half* C = (__half*)g_scratch + cOffH + (long)blockIdx.z * sC;
        #pragma unroll
        for (int mt = 0; mt < 4; mt++) {
            const long row0 = bm + wm + mt * 16 + r;
            #pragma unroll
            for (int nt = 0; nt < 8; nt++) {
                const int col = bn + wn + nt * 8 + 2 * c;
                const __half2 h0 = __floats2half2_rn(acc[mt][nt][0] * alpha,
                                                     acc[mt][nt][1] * alpha);
                const __half2 h1 = __floats2half2_rn(acc[mt][nt][2] * alpha,
                                                     acc[mt][nt][3] * alpha);
                *reinterpret_cast<__half2*>(C + row0 * ldc + col)       = h0;
                *reinterpret_cast<__half2*>(C + (row0 + 8) * ldc + col) = h1;
            }
        }
    } else {
        float* C = CextF;
        #pragma unroll
        for (int mt = 0; mt < 4; mt++) {
            const long row0 = bm + wm + mt * 16 + r;
            #pragma unroll
            for (int nt = 0; nt < 8; nt++) {
                const int col = bn + wn + nt * 8 + 2 * c;
                float bx = 0.f, by = 0.f;
                if (BIAS) { bx = bias[col]; by = bias[col + 1]; }
                float2 v0, v1;
                v0.x = acc[mt][nt][0] * alpha + bx;
                v0.y = acc[mt][nt][1] * alpha + by;
                v1.x = acc[mt][nt][2] * alpha + bx;
                v1.y = acc[mt][nt][3] * alpha + by;
                *reinterpret_cast<float2*>(C + row0 * ldc + col)       = v0;
                *reinterpret_cast<float2*>(C + (row0 + 8) * ldc + col) = v1;
            }
        }
    }
}

// ---------------------------------------------------------------------------
// Row softmax on fp16 rows (compute fp32): one block per 2048-long row.
// ---------------------------------------------------------------------------
__global__ __launch_bounds__(256)
void softmax_h(long sOffH)
{
    __half* row = (__half*)g_scratch + sOffH + (long)blockIdx.x * 2048;
    const int tid = threadIdx.x;

    uint4 raw = *reinterpret_cast<const uint4*>(row + tid * 8);
    const __half2* hp = reinterpret_cast<const __half2*>(&raw);
    float vals[8];
    float m = -INFINITY;
    #pragma unroll
    for (int i = 0; i < 4; i++) {
        const float2 f = __half22float2(hp[i]);
        vals[i * 2] = f.x; vals[i * 2 + 1] = f.y;
        m = fmaxf(m, fmaxf(f.x, f.y));
    }
    __shared__ float red_max[8];
    __shared__ float red_sum[8];
    #pragma unroll
    for (int o = 16; o; o >>= 1) m = fmaxf(m, __shfl_xor_sync(0xFFFFFFFFu, m, o));
    if ((tid & 31) == 0) red_max[tid >> 5] = m;
    __syncthreads();
    m = red_max[0];
    #pragma unroll
    for (int i = 1; i < 8; i++) m = fmaxf(m, red_max[i]);

    float sum = 0.f;
    #pragma unroll
    for (int i = 0; i < 8; i++) {
        vals[i] = expf(vals[i] - m);
        sum += vals[i];
    }
    #pragma unroll
    for (int o = 16; o; o >>= 1) sum += __shfl_xor_sync(0xFFFFFFFFu, sum, o);
    if ((tid & 31) == 0) red_sum[tid >> 5] = sum;
    __syncthreads();
    sum = 0.f;
    #pragma unroll
    for (int i = 0; i < 8; i++) sum += red_sum[i];

    const float inv = 1.0f / sum;
    __half2 out[4];
    #pragma unroll
    for (int i = 0; i < 4; i++)
        out[i] = __floats2half2_rn(vals[i * 2] * inv, vals[i * 2 + 1] * inv);
    *reinterpret_cast<uint4*>(row + tid * 8) = *reinterpret_cast<uint4*>(out);
}

// ---------------------------------------------------------------------------
// Launch
// ---------------------------------------------------------------------------
extern "C" void kernel_launch(void* const* d_in, const int* in_sizes, int n_in,
                              void* d_out, int out_size)
{
    const float* x       = (const float*)d_in[0];  // (4,2048,2048)
    const float* w_qk    = (const float*)d_in[1];  // (4096,2048)
    const float* w_dense = (const float*)d_in[2];  // (2048,2048)
    const float* b_dense = (const float*)d_in[3];  // (2048,)
    float* out = (float*)d_out;

    const float scale = (float)(1.0 / sqrt((double)2048 * 2047 / 2.0));
    const int SMEM_H = 3 * 2 * 128 * 72 * 2;   // 110592 bytes

    cudaFuncSetAttribute(hgemm<false,false,true>,
                         cudaFuncAttributeMaxDynamicSharedMemorySize, SMEM_H);
    cudaFuncSetAttribute(hgemm<true,true,false>,
                         cudaFuncAttributeMaxDynamicSharedMemorySize, SMEM_H);

    // 0) round inputs to fp16
    round_copy_h<<<8192, 256>>>(x,       H_XH,   2097152);
    round_copy_h<<<4096, 256>>>(w_qk,    H_WQKH, 1048576);
    round_copy_h<<<2048, 256>>>(w_dense, H_WDH,   524288);

    // 1) kvh = xh @ wqkh^T : M=8192 N=4096 K=2048
    hgemm<false,false,true><<<dim3(32, 64, 1), 128, SMEM_H>>>(
        H_XH, H_WQKH, nullptr, H_KVH,
        2048, 2048, 2048, 4096, 0, 0, 0, 1.0f, nullptr);

    // 2) k0T / vT transposes (per batch)
    transpose_kv<<<dim3(32, 32, 8), 256>>>();

    // 3) s[b] = k0T[b] @ v[b](rows) * scale   (fp16 out)
    hgemm<false,false,true><<<dim3(16, 16, 4), 128, SMEM_H>>>(
        H_K0T, H_KVH + 2048, nullptr, H_SH,
        2048, 2048, 4096, 2048,
        (long)2048 * 2048, (long)2048 * 4096, (long)2048 * 2048, scale, nullptr);

    // 4) softmax rows (in place)
    softmax_h<<<8192, 256>>>(H_SH);

    // 5) q[b] = a[b] @ vT[b](rows)            (fp16 out)
    hgemm<false,false,true><<<dim3(16, 16, 4), 128, SMEM_H>>>(
        H_SH, H_VT, nullptr, H_QH,
        2048, 2048, 2048, 2048,
        (long)2048 * 2048, (long)2048 * 2048, (long)2048 * 2048, 1.0f, nullptr);

    // 6) out = gather_perm(q) @ wdh^T + b_dense   (fp32 out)
    hgemm<true,true,false><<<dim3(16, 64, 1), 128, SMEM_H>>>(
        H_QH, H_WDH, out, 0,
        2048, 2048, 2048, 2048, 0, 0, 0, 1.0f, b_dense);
}